// round 5
// baseline (speedup 1.0000x reference)
#include <cuda_runtime.h>

#define S_   500
#define XY_  10
#define ZD_  5
#define NT_  10000
#define B_   32
#define T_   40
#define L_   20

// Scratch (allocation-free rule: __device__ globals)
__device__ float g_LET[NT_ * S_];      // transposed emissions [NT, S] (~20 MB)
__device__ float g_em[B_ * T_ * S_];   // per-(b,t) emission sums (~2.56 MB)

// ---------------------------------------------------------------------------
// Kernel 1: transpose log_emissions [S, NT] -> g_LET [NT, S]
// ---------------------------------------------------------------------------
__global__ void k_transpose(const float* __restrict__ LE) {
    __shared__ float tile[32][33];
    const int tBase = blockIdx.x * 32;   // token dim
    const int sBase = blockIdx.y * 32;   // state dim
    const int tx = threadIdx.x, ty = threadIdx.y;

    #pragma unroll
    for (int k = 0; k < 32; k += 8) {
        int s = sBase + ty + k;
        int t = tBase + tx;
        float v = 0.f;
        if (s < S_ && t < NT_) v = LE[s * NT_ + t];   // coalesced over tx
        tile[ty + k][tx] = v;
    }
    __syncthreads();
    #pragma unroll
    for (int k = 0; k < 32; k += 8) {
        int t = tBase + ty + k;
        int s = sBase + tx;
        if (s < S_ && t < NT_) g_LET[t * S_ + s] = tile[tx][ty + k];  // coalesced over tx
    }
}

// ---------------------------------------------------------------------------
// Kernel 2: em[b,t,s] = sum_l LET[tok[b,t,l], s]   (one block per (b,t))
// ---------------------------------------------------------------------------
__global__ void k_em(const int* __restrict__ stories) {
    const int bt = blockIdx.x;             // b*T + t
    __shared__ int toks[L_];
    if (threadIdx.x < L_) toks[threadIdx.x] = stories[bt * L_ + threadIdx.x];
    __syncthreads();
    const int s = threadIdx.x;
    if (s < S_) {
        float acc = 0.f;
        #pragma unroll
        for (int l = 0; l < L_; l++)
            acc += g_LET[toks[l] * S_ + s];   // coalesced rows, table L2-resident
        g_em[bt * S_ + s] = acc;
    }
}

// ---------------------------------------------------------------------------
// Kernel 3: forward recursion. One CTA per batch, alpha in SMEM ping-pong.
// Sparse 7-neighbor logsumexp with per-row max (matches dense reference:
// the -1e9 entries contribute exp(<-800)=0 exactly in fp32).
// ---------------------------------------------------------------------------
__global__ __launch_bounds__(512, 1)
void k_forward(const float* __restrict__ priors,
               const float* __restrict__ logT,
               float* __restrict__ out) {
    __shared__ float bufA[S_];
    __shared__ float bufB[S_];
    const int b = blockIdx.x;
    const int s = threadIdx.x;

    int   jn[7];
    float tv[7];

    if (s < S_) {
        const int z = s / 100, r = s % 100, y = r / 10, x = r % 10;
        const int dx[7] = {0, 1,-1, 0, 0, 0, 0};
        const int dy[7] = {0, 0, 0, 1,-1, 0, 0};
        const int dz[7] = {0, 0, 0, 0, 0, 1, 2};
        #pragma unroll
        for (int d = 0; d < 7; d++) {
            int nx = x + dx[d], ny = y + dy[d], nz = z + dz[d];
            bool v = ((unsigned)nx < XY_) & ((unsigned)ny < XY_) & ((unsigned)nz < ZD_);
            int jj = v ? (nx + XY_ * (ny + XY_ * nz)) : s;
            jn[d] = jj;
            tv[d] = v ? logT[s * S_ + jj] : -1e9f;
        }
        // t = 0
        float a0 = g_em[(b * T_ + 0) * S_ + s] + priors[s];
        out[0 * B_ * S_ + b * S_ + s] = a0;
        bufA[s] = a0;
    }
    __syncthreads();

    float* cur = bufA;
    float* nxt = bufB;

    float em_next = (s < S_) ? g_em[(b * T_ + 1) * S_ + s] : 0.f;

    for (int t = 1; t < T_; t++) {
        float emv = em_next;
        if (t + 1 < T_ && s < S_) em_next = g_em[(b * T_ + t + 1) * S_ + s]; // prefetch

        if (s < S_) {
            float v0 = tv[0] + cur[jn[0]];
            float v1 = tv[1] + cur[jn[1]];
            float v2 = tv[2] + cur[jn[2]];
            float v3 = tv[3] + cur[jn[3]];
            float v4 = tv[4] + cur[jn[4]];
            float v5 = tv[5] + cur[jn[5]];
            float v6 = tv[6] + cur[jn[6]];
            float m = fmaxf(fmaxf(fmaxf(v0, v1), fmaxf(v2, v3)),
                            fmaxf(fmaxf(v4, v5), v6));
            float sum = __expf(v0 - m) + __expf(v1 - m) + __expf(v2 - m)
                      + __expf(v3 - m) + __expf(v4 - m) + __expf(v5 - m)
                      + __expf(v6 - m);
            float anew = emv + m + __logf(sum);
            out[t * B_ * S_ + b * S_ + s] = anew;
            nxt[s] = anew;
        }
        __syncthreads();
        float* tmp = cur; cur = nxt; nxt = tmp;
    }
}

// ---------------------------------------------------------------------------
extern "C" void kernel_launch(void* const* d_in, const int* in_sizes, int n_in,
                              void* d_out, int out_size) {
    const float* log_priors      = (const float*)d_in[0];
    const float* log_transitions = (const float*)d_in[1];
    const float* log_emissions   = (const float*)d_in[2];
    const int*   stories         = (const int*)d_in[3];
    float* out = (float*)d_out;

    {
        dim3 grid((NT_ + 31) / 32, (S_ + 31) / 32);
        dim3 block(32, 8);
        k_transpose<<<grid, block>>>(log_emissions);
    }
    k_em<<<B_ * T_, 512>>>(stories);
    k_forward<<<B_, 512>>>(log_priors, log_transitions, out);
}